// round 15
// baseline (speedup 1.0000x reference)
#include <cuda_runtime.h>
#include <cuda_bf16.h>
#include <cuda_fp16.h>
#include <math.h>
#include <stdint.h>

#define NN 50000
#define NE 800000
#define NODE_F 128
#define EDGE_F 32
#define TIME_D 16
#define K1 176
#define DN 128

typedef unsigned long long ull;

// ---------------- scratch ----------------
__device__ float g_agg[(size_t)NN * 128];
__device__ float g_cnt[NN];
__device__ uint32_t g_yf16[(size_t)NN * 64];        // Y = x @ W1x, f16x2, 4x4-block-permuted
__device__ uint32_t g_tfrag[(size_t)NE * 24];       // tail in fragment order [tile][p][lane]
__device__ uint32_t g_wf16[4 * 128 * 64];           // node weights f16x2: r, z, n, out

// ---------------- helpers ----------------
__device__ __forceinline__ uint32_t smem_u32(const void* p) {
    uint32_t a;
    asm("{ .reg .u64 t; cvta.to.shared.u64 t, %1; cvt.u32.u64 %0, t; }" : "=r"(a) : "l"(p));
    return a;
}
__device__ __forceinline__ float sigm(float x) { return 1.0f / (1.0f + expf(-x)); }

__device__ __forceinline__ uint32_t h2u(float a, float b) {
    __half2 h = __floats2half2_rn(a, b);
    return *reinterpret_cast<uint32_t*>(&h);
}

__device__ __forceinline__ void ldsm_x4(uint32_t& r0, uint32_t& r1, uint32_t& r2, uint32_t& r3,
                                        uint32_t addr) {
    asm volatile("ldmatrix.sync.aligned.m8n8.x4.shared.b16 {%0,%1,%2,%3}, [%4];"
                 : "=r"(r0), "=r"(r1), "=r"(r2), "=r"(r3) : "r"(addr));
}
__device__ __forceinline__ void mma_f16(float* d, const uint32_t* a, const uint32_t* b) {
    asm volatile("mma.sync.aligned.m16n8k16.row.col.f32.f16.f16.f32 "
                 "{%0,%1,%2,%3}, {%4,%5,%6,%7}, {%8,%9}, {%0,%1,%2,%3};"
                 : "+f"(d[0]), "+f"(d[1]), "+f"(d[2]), "+f"(d[3])
                 : "r"(a[0]), "r"(a[1]), "r"(a[2]), "r"(a[3]), "r"(b[0]), "r"(b[1]));
}
#define GBAR(id)    asm volatile("bar.sync %0, 128;" :: "r"(id) : "memory")

// ---------------- zero scratch ----------------
__global__ void zero_kernel() {
    int i = blockIdx.x * blockDim.x + threadIdx.x;
    int stride = gridDim.x * blockDim.x;
    float4 z = make_float4(0.f, 0.f, 0.f, 0.f);
    float4* a4 = reinterpret_cast<float4*>(g_agg);
    for (int j = i; j < NN * 128 / 4; j += stride) a4[j] = z;
    for (int j = i; j < NN; j += stride) g_cnt[j] = 0.f;
}

// ================= PREP KERNEL: edge-pre | Y-gemm | weight-convert =================
#define NPRE (NE / 256)            // 3125
#define NYB  ((NN + 63) / 64)      // 782
#define NWB  8
#define PREP_SMEM_BYTES 52352

#define YW 0          // [128][136] f16 = 34816
#define YA 34816      // [64][136]  f16 = 17408

__global__ __launch_bounds__(256)
void prep_kernel(const float* __restrict__ eattr, const float* __restrict__ tt,
                 const float* __restrict__ tw, const float* __restrict__ tb,
                 const int* __restrict__ ei, const float* __restrict__ x,
                 const float* __restrict__ w1, const float* __restrict__ wih,
                 const float* __restrict__ ow)
{
    extern __shared__ char smc[];
    const int b = blockIdx.x;
    const int tid = threadIdx.x;

    if (b < NPRE) {
        uint32_t* st = (uint32_t*)smc;     // [256][25]
        const int e = b * 256 + tid;

        uint32_t th[24];
        const float4* er = (const float4*)(eattr + (size_t)e * 32);
#pragma unroll
        for (int i = 0; i < 8; ++i) {
            float4 f = __ldg(&er[i]);
            th[2 * i]     = h2u(f.x, f.y);
            th[2 * i + 1] = h2u(f.z, f.w);
        }
        float tv = __ldg(&tt[e]);
#pragma unroll
        for (int d = 0; d < 8; ++d) {
            float a = cosf(tv * __ldg(&tw[2 * d])     + __ldg(&tb[2 * d]));
            float bb = cosf(tv * __ldg(&tw[2 * d + 1]) + __ldg(&tb[2 * d + 1]));
            th[16 + d] = h2u(a, bb);
        }
#pragma unroll
        for (int j = 0; j < 24; ++j) st[tid * 25 + j] = th[j];
        atomicAdd(&g_cnt[__ldg(&ei[NE + e])], 1.0f);
        __syncthreads();

        const int tl = tid >> 5, L = tid & 31;
        uint32_t* dst = g_tfrag + ((size_t)b * 8 + tl) * 768 + L;
#pragma unroll
        for (int p = 0; p < 24; ++p) {
            const int mfks = p >> 2, rsel = p & 3;
            const int mf = mfks / 3, ks = mfks - mf * 3;
            const int esel = rsel & 1, part = rsel >> 1;
            const int r = mf * 16 + esel * 8 + (L >> 2);
            const int j = ks * 8 + part * 4 + (L & 3);
            dst[p * 32] = st[(tl * 32 + r) * 25 + j];
        }
    } else if (b < NPRE + NYB) {
        const uint32_t smb = smem_u32(smc);
        const int wid = tid >> 5, lane = tid & 31;
        const int m0 = (wid & 3) * 16, nbase = (wid >> 2) * 64;
        const int base = (b - NPRE) * 64;
        const int crow = lane >> 2, ccol = (lane & 3) * 2;

        for (int idx = tid; idx < 128 * 128; idx += 256) {
            int k = idx >> 7, n = idx & 127;
            *(__half*)(smc + YW + 2 * (n * 136 + k)) = __float2half_rn(w1[k * 128 + n]);
        }
        for (int idx = tid; idx < 64 * 64; idx += 256) {
            int m = idx >> 6, kp = idx & 63;
            int row = base + m;
            uint32_t v = 0u;
            if (row < NN)
                v = h2u(__ldg(&x[(size_t)row * 128 + 2 * kp]),
                        __ldg(&x[(size_t)row * 128 + 2 * kp + 1]));
            *(uint32_t*)(smc + YA + 2 * (m * 136 + 2 * kp)) = v;
        }
        __syncthreads();

        const uint32_t aRow = (uint32_t)((m0 + (lane & 15)) * 136 + ((lane >> 4) << 3)) * 2;
        const uint32_t bRow = (uint32_t)((lane & 7) + ((lane >> 4) << 3));
        const uint32_t bLane = (uint32_t)(bRow * 136 + (((lane >> 3) & 1) << 3)) * 2;

        float acc[8][4];
#pragma unroll
        for (int j = 0; j < 8; ++j)
#pragma unroll
            for (int q = 0; q < 4; ++q) acc[j][q] = 0.f;

#pragma unroll
        for (int ks = 0; ks < 8; ++ks) {
            const uint32_t kOff = (uint32_t)(ks * 16) * 2;
            uint32_t a[4];
            ldsm_x4(a[0], a[1], a[2], a[3], smb + YA + aRow + kOff);
#pragma unroll
            for (int jj = 0; jj < 4; ++jj) {
                const uint32_t nOff = (uint32_t)((nbase + jj * 16) * 136) * 2;
                uint32_t bb[4];
                ldsm_x4(bb[0], bb[1], bb[2], bb[3], smb + YW + bLane + nOff + kOff);
                mma_f16(acc[2 * jj],     a, bb);
                mma_f16(acc[2 * jj + 1], a, bb + 2);
            }
        }

        int r0 = m0 + crow, r1 = r0 + 8;
        int nd0 = base + r0, nd1 = base + r1;
#pragma unroll
        for (int j = 0; j < 8; ++j) {
            int c = (nbase + j * 8 + ccol) >> 1;
            int p = (c & ~15) | ((c & 3) << 2) | ((c >> 2) & 3);   // 4x4 block transpose
            if (nd0 < NN) g_yf16[(size_t)nd0 * 64 + p] = h2u(acc[j][0], acc[j][1]);
            if (nd1 < NN) g_yf16[(size_t)nd1 * 64 + p] = h2u(acc[j][2], acc[j][3]);
        }
    } else {
        const int wb = b - NPRE - NYB;       // 0..7
#pragma unroll
        for (int it = 0; it < 16; ++it) {
            int i = wb * 4096 + it * 256 + tid;
            int mat = i >> 13;
            int r = (i >> 6) & 127;
            int kp = i & 63;
            const float* src = (mat < 3) ? (wih + mat * 16384) : ow;
            g_wf16[i] = h2u(__ldg(&src[r * 128 + 2 * kp]), __ldg(&src[r * 128 + 2 * kp + 1]));
        }
    }
}

// ================= EDGE KERNEL (unchanged from R14) =================
#define EK_M   32
#define NT32   (NE / EK_M)
#define NGRP   3
#define LDAT   56
#define LDH    136

#define SM_W1T 0
#define SM_W2  14336
#define SM_H   49152
#define SM_B1  75264
#define SM_B2  75776
#define EDGE_SMEM_BYTES 76288

__global__ __launch_bounds__(384, 1)
void edge_kernel(const float* __restrict__ w1, const float* __restrict__ b1,
                 const float* __restrict__ w2, const float* __restrict__ b2,
                 const int* __restrict__ ei)
{
    extern __shared__ char smc[];
    const uint32_t smb = smem_u32(smc);
    const int tid = threadIdx.x;
    const int wid = tid >> 5, lane = tid & 31;
    const int grp = wid >> 2;
    const int gw = wid & 3;
    const int nbase = gw * 32;

    float* b1s = (float*)(smc + SM_B1);
    float* b2s = (float*)(smc + SM_B2);

    for (int idx = tid; idx < 48 * DN; idx += 384) {
        int k = idx >> 7, n = idx & 127;
        *(__half*)(smc + SM_W1T + 2 * (n * LDAT + k)) = __float2half_rn(w1[(128 + k) * 128 + n]);
    }
    for (int idx = tid; idx < DN * DN; idx += 384) {
        int k = idx >> 7, n = idx & 127;
        *(__half*)(smc + SM_W2 + 2 * (n * LDH + k)) = __float2half_rn(w2[idx]);
    }
    for (int i = tid; i < 128; i += 384) { b1s[i] = b1[i]; b2s[i] = b2[i]; }
    __syncthreads();

    const int barId = 1 + grp;
    const uint32_t hBase = smb + SM_H + grp * 8704;

    const uint32_t hRow0 = (uint32_t)((lane & 15) * LDH + ((lane >> 4) << 3)) * 2;
    const uint32_t hRow1 = hRow0 + (uint32_t)(16 * LDH) * 2;
    const uint32_t bRow = (uint32_t)((lane & 7) + ((lane >> 4) << 3));
    const uint32_t bColPiece = (uint32_t)(((lane >> 3) & 1) << 3);
    const uint32_t b1LaneOff = (uint32_t)(bRow * LDAT + bColPiece) * 2;
    const uint32_t b2LaneOff = (uint32_t)(bRow * LDH + bColPiece) * 2;
    const int crow = lane >> 2;
    const int ccol = (lane & 3) * 2;
    const int yoff = gw * 16 + (lane & 3) * 4;

    uint32_t w1f[24];
#pragma unroll
    for (int ks = 0; ks < 3; ++ks)
#pragma unroll
        for (int jj = 0; jj < 2; ++jj)
            ldsm_x4(w1f[(ks * 2 + jj) * 4], w1f[(ks * 2 + jj) * 4 + 1],
                    w1f[(ks * 2 + jj) * 4 + 2], w1f[(ks * 2 + jj) * 4 + 3],
                    smb + SM_W1T + b1LaneOff + (uint32_t)((nbase + jj * 16) * LDAT) * 2
                    + (uint32_t)(ks * 32));

    int tile = blockIdx.x * NGRP + grp;
    const int step = gridDim.x * NGRP;

    uint32_t tailA[24], tailN[24];
    if (tile < NT32) {
        const uint32_t* tf = g_tfrag + (size_t)tile * 768 + lane;
#pragma unroll
        for (int p = 0; p < 24; ++p) tailA[p] = __ldg(&tf[p * 32]);
    }

    for (; tile < NT32; tile += step) {
        const int ebase = tile * EK_M;

        int s00 = __ldg(&ei[ebase + crow]);
        int s01 = __ldg(&ei[ebase + crow + 8]);
        int s10 = __ldg(&ei[ebase + 16 + crow]);
        int s11 = __ldg(&ei[ebase + 24 + crow]);
        int t00 = __ldg(&ei[NE + ebase + crow]);
        int t01 = __ldg(&ei[NE + ebase + crow + 8]);
        int t10 = __ldg(&ei[NE + ebase + 16 + crow]);
        int t11 = __ldg(&ei[NE + ebase + 24 + crow]);

        uint4 Y4[4];
        Y4[0] = __ldg((const uint4*)&g_yf16[(size_t)s00 * 64 + yoff]);
        Y4[1] = __ldg((const uint4*)&g_yf16[(size_t)s01 * 64 + yoff]);
        Y4[2] = __ldg((const uint4*)&g_yf16[(size_t)s10 * 64 + yoff]);
        Y4[3] = __ldg((const uint4*)&g_yf16[(size_t)s11 * 64 + yoff]);

        float acc[2][4][4];
#pragma unroll
        for (int i = 0; i < 2; ++i)
#pragma unroll
            for (int j = 0; j < 4; ++j)
#pragma unroll
                for (int q = 0; q < 4; ++q) acc[i][j][q] = 0.f;

#pragma unroll
        for (int ks = 0; ks < 3; ++ks) {
#pragma unroll
            for (int jj = 0; jj < 2; ++jj) {
                const uint32_t* b = &w1f[(ks * 2 + jj) * 4];
                mma_f16(acc[0][jj * 2],     &tailA[(0 * 3 + ks) * 4], b);
                mma_f16(acc[0][jj * 2 + 1], &tailA[(0 * 3 + ks) * 4], b + 2);
                mma_f16(acc[1][jj * 2],     &tailA[(1 * 3 + ks) * 4], b);
                mma_f16(acc[1][jj * 2 + 1], &tailA[(1 * 3 + ks) * 4], b + 2);
            }
        }

        {
            const int nxt = tile + step;
            if (nxt < NT32) {
                const uint32_t* tf = g_tfrag + (size_t)nxt * 768 + lane;
#pragma unroll
                for (int p = 0; p < 24; ++p) tailN[p] = __ldg(&tf[p * 32]);
            }
        }

#pragma unroll
        for (int mf = 0; mf < 2; ++mf) {
            int r0 = mf * 16 + crow, r1 = r0 + 8;
#pragma unroll
            for (int j = 0; j < 4; ++j) {
                int n = nbase + j * 8 + ccol;
                uint32_t yu0 = ((const uint32_t*)&Y4[mf * 2 + 0])[j];
                uint32_t yu1 = ((const uint32_t*)&Y4[mf * 2 + 1])[j];
                __half2 y0 = *reinterpret_cast<__half2*>(&yu0);
                __half2 y1 = *reinterpret_cast<__half2*>(&yu1);
                float v0 = fmaxf(acc[mf][j][0] + __low2float(y0)  + b1s[n],     0.f);
                float v1 = fmaxf(acc[mf][j][1] + __high2float(y0) + b1s[n + 1], 0.f);
                float v2 = fmaxf(acc[mf][j][2] + __low2float(y1)  + b1s[n],     0.f);
                float v3 = fmaxf(acc[mf][j][3] + __high2float(y1) + b1s[n + 1], 0.f);
                *(__half2*)(smc + (hBase - smb) + 2 * (r0 * LDH + n)) = __floats2half2_rn(v0, v1);
                *(__half2*)(smc + (hBase - smb) + 2 * (r1 * LDH + n)) = __floats2half2_rn(v2, v3);
            }
        }
        GBAR(barId);

#pragma unroll
        for (int i = 0; i < 2; ++i)
#pragma unroll
            for (int j = 0; j < 4; ++j)
#pragma unroll
                for (int q = 0; q < 4; ++q) acc[i][j][q] = 0.f;

#pragma unroll
        for (int ks = 0; ks < 8; ++ks) {
            const uint32_t kOff = (uint32_t)(ks * 16) * 2;
            uint32_t a0[4], a1[4];
            ldsm_x4(a0[0], a0[1], a0[2], a0[3], hBase + hRow0 + kOff);
            ldsm_x4(a1[0], a1[1], a1[2], a1[3], hBase + hRow1 + kOff);
#pragma unroll
            for (int jj = 0; jj < 2; ++jj) {
                const uint32_t nOff = (uint32_t)((nbase + jj * 16) * LDH) * 2;
                uint32_t b[4];
                ldsm_x4(b[0], b[1], b[2], b[3], smb + SM_W2 + b2LaneOff + nOff + kOff);
                mma_f16(acc[0][jj * 2],     a0, b);
                mma_f16(acc[0][jj * 2 + 1], a0, b + 2);
                mma_f16(acc[1][jj * 2],     a1, b);
                mma_f16(acc[1][jj * 2 + 1], a1, b + 2);
            }
        }

#pragma unroll
        for (int mf = 0; mf < 2; ++mf) {
            int tg0 = (mf == 0) ? t00 : t10;
            int tg1 = (mf == 0) ? t01 : t11;
            size_t ga0 = __cvta_generic_to_global(&g_agg[(size_t)tg0 * 128]);
            size_t ga1 = __cvta_generic_to_global(&g_agg[(size_t)tg1 * 128]);
#pragma unroll
            for (int j = 0; j < 4; ++j) {
                int n = nbase + j * 8 + ccol;
                float v0 = acc[mf][j][0] + b2s[n];
                float v1 = acc[mf][j][1] + b2s[n + 1];
                float v2 = acc[mf][j][2] + b2s[n];
                float v3 = acc[mf][j][3] + b2s[n + 1];
                asm volatile("red.global.add.v2.f32 [%0], {%1,%2};"
                             :: "l"(ga0 + (size_t)n * 4), "f"(v0), "f"(v1) : "memory");
                asm volatile("red.global.add.v2.f32 [%0], {%1,%2};"
                             :: "l"(ga1 + (size_t)n * 4), "f"(v2), "f"(v3) : "memory");
            }
        }
        GBAR(barId);

#pragma unroll
        for (int i = 0; i < 24; ++i) tailA[i] = tailN[i];
    }
}

// ================= NODE KERNEL (persistent, all weights resident, 1 CTA/SM) =================
#define NLDB 136
#define NW4  0            // 4 * 34816 = 139264 (r, z, n, out)
#define NVS  139264       // [64][136] f16 = 17408
#define NMS  156672       // 17408
#define NODE_SMEM_BYTES 174080
#define NTILES ((NN + 63) / 64)   // 782

__device__ __forceinline__ void hgemm1_128(uint32_t bBase, uint32_t aAddr,
                                           int nbase, float acc[8][4]) {
#pragma unroll
    for (int j = 0; j < 8; ++j)
#pragma unroll
        for (int q = 0; q < 4; ++q) acc[j][q] = 0.f;
#pragma unroll
    for (int ks = 0; ks < 8; ++ks) {
        const uint32_t kOff = (uint32_t)(ks * 16) * 2;
        uint32_t a[4];
        ldsm_x4(a[0], a[1], a[2], a[3], aAddr + kOff);
#pragma unroll
        for (int jj = 0; jj < 4; ++jj) {
            const uint32_t nOff = (uint32_t)((nbase + jj * 16) * NLDB) * 2;
            uint32_t b[4];
            ldsm_x4(b[0], b[1], b[2], b[3], bBase + nOff + kOff);
            mma_f16(acc[2 * jj],     a, b);
            mma_f16(acc[2 * jj + 1], a, b + 2);
        }
    }
}

__global__ __launch_bounds__(256, 1)
void node_kernel(const float* __restrict__ bih, const float* __restrict__ bhh,
                 const float* __restrict__ ob, float* __restrict__ out)
{
    extern __shared__ char smc[];
    const uint32_t smb = smem_u32(smc);
    const int tid = threadIdx.x, wid = tid >> 5, lane = tid & 31;
    const int m0 = (wid & 3) * 16, nbase = (wid >> 2) * 64;
    const int crow = lane >> 2, ccol = (lane & 3) * 2;

    // ---- stage ALL weights once (8192 uint4) ----
    {
        const uint4* src = (const uint4*)g_wf16;
        for (int idx = tid; idx < 8192; idx += 256) {
            int mat = idx >> 11;
            int rem = idx & 2047;
            int n = rem >> 4, g = rem & 15;
            uint4 v = __ldg(&src[idx]);
            *(uint4*)(smc + NW4 + mat * 34816 + n * (NLDB * 2) + g * 16) = v;
        }
    }

    const uint32_t aRow = (uint32_t)((m0 + (lane & 15)) * NLDB + ((lane >> 4) << 3)) * 2;
    const uint32_t bRow = (uint32_t)((lane & 7) + ((lane >> 4) << 3));
    const uint32_t bLane = (uint32_t)(bRow * NLDB + (((lane >> 3) & 1) << 3)) * 2;

    const uint32_t bR = smb + NW4 + 0 * 34816 + bLane;
    const uint32_t bZ = smb + NW4 + 1 * 34816 + bLane;
    const uint32_t bN = smb + NW4 + 2 * 34816 + bLane;
    const uint32_t bO = smb + NW4 + 3 * 34816 + bLane;

    __syncthreads();   // weights ready (also covers first V-tile write below)

    for (int tile = blockIdx.x; tile < NTILES; tile += gridDim.x) {
        const int base = tile * 64;

        // ---- V tile (mean-aggregated, f16) ----
        for (int idx = tid; idx < 64 * 64; idx += 256) {
            int m = idx >> 6, kp = idx & 63;
            int nd = base + m;
            float a0 = 0.f, a1 = 0.f;
            if (nd < NN) {
                float inv = 1.0f / fmaxf(g_cnt[nd], 1.0f);
                a0 = g_agg[(size_t)nd * 128 + 2 * kp] * inv;
                a1 = g_agg[(size_t)nd * 128 + 2 * kp + 1] * inv;
            }
            *(uint32_t*)(smc + NVS + 2 * (m * NLDB + 2 * kp)) = h2u(a0, a1);
        }
        __syncthreads();

        float acc[8][4], rg[8][4], ng[8][4];

        // ---- r gate ----
        hgemm1_128(bR, smb + NVS + aRow, nbase, acc);
#pragma unroll
        for (int j = 0; j < 8; ++j) {
            int n = nbase + j * 8 + ccol;
            rg[j][0] = sigm(acc[j][0] + __ldg(&bih[n])     + __ldg(&bhh[n]));
            rg[j][1] = sigm(acc[j][1] + __ldg(&bih[n + 1]) + __ldg(&bhh[n + 1]));
            rg[j][2] = sigm(acc[j][2] + __ldg(&bih[n])     + __ldg(&bhh[n]));
            rg[j][3] = sigm(acc[j][3] + __ldg(&bih[n + 1]) + __ldg(&bhh[n + 1]));
        }

        // ---- n gate ----
        hgemm1_128(bN, smb + NVS + aRow, nbase, acc);
#pragma unroll
        for (int j = 0; j < 8; ++j) {
            int n = 256 + nbase + j * 8 + ccol;
            ng[j][0] = tanhf(acc[j][0] + __ldg(&bih[n])     + rg[j][0] * __ldg(&bhh[n]));
            ng[j][1] = tanhf(acc[j][1] + __ldg(&bih[n + 1]) + rg[j][1] * __ldg(&bhh[n + 1]));
            ng[j][2] = tanhf(acc[j][2] + __ldg(&bih[n])     + rg[j][2] * __ldg(&bhh[n]));
            ng[j][3] = tanhf(acc[j][3] + __ldg(&bih[n + 1]) + rg[j][3] * __ldg(&bhh[n + 1]));
        }

        // ---- z gate + memory = (1-z)*n -> Ms ----
        hgemm1_128(bZ, smb + NVS + aRow, nbase, acc);
        {
            int r0 = m0 + crow, r1 = m0 + crow + 8;
#pragma unroll
            for (int j = 0; j < 8; ++j) {
                int nl = nbase + j * 8 + ccol;
                int n = 128 + nl;
                float z0 = sigm(acc[j][0] + __ldg(&bih[n])     + __ldg(&bhh[n]));
                float z1 = sigm(acc[j][1] + __ldg(&bih[n + 1]) + __ldg(&bhh[n + 1]));
                float z2 = sigm(acc[j][2] + __ldg(&bih[n])     + __ldg(&bhh[n]));
                float z3 = sigm(acc[j][3] + __ldg(&bih[n + 1]) + __ldg(&bhh[n + 1]));
                *(uint32_t*)(smc + NMS + 2 * (r0 * NLDB + nl)) =
                    h2u((1.f - z0) * ng[j][0], (1.f - z1) * ng[j][1]);
                *(uint32_t*)(smc + NMS + 2 * (r1 * NLDB + nl)) =
                    h2u((1.f - z2) * ng[j][2], (1.f - z3) * ng[j][3]);
            }
        }
        __syncthreads();

        // ---- out projection ----
        hgemm1_128(bO, smb + NMS + aRow, nbase, acc);
        {
            int r0 = m0 + crow, r1 = m0 + crow + 8;
            int nd0 = base + r0, nd1 = base + r1;
#pragma unroll
            for (int j = 0; j < 8; ++j) {
                int n = nbase + j * 8 + ccol;
                float o0 = __ldg(&ob[n]), o1 = __ldg(&ob[n + 1]);
                if (nd0 < NN)
                    *(float2*)&out[(size_t)nd0 * 128 + n] = make_float2(acc[j][0] + o0, acc[j][1] + o1);
                if (nd1 < NN)
                    *(float2*)&out[(size_t)nd1 * 128 + n] = make_float2(acc[j][2] + o0, acc[j][3] + o1);
            }
        }
        __syncthreads();   // Ms/Vs fully consumed before next tile overwrites
    }
}

// ================= launch =================
extern "C" void kernel_launch(void* const* d_in, const int* in_sizes, int n_in,
                              void* d_out, int out_size) {
    const float* x     = (const float*)d_in[0];
    const float* eattr = (const float*)d_in[1];
    const float* t     = (const float*)d_in[2];
    const float* tw    = (const float*)d_in[3];
    const float* tb    = (const float*)d_in[4];
    const float* w1    = (const float*)d_in[5];
    const float* b1    = (const float*)d_in[6];
    const float* w2    = (const float*)d_in[7];
    const float* b2    = (const float*)d_in[8];
    const float* wih   = (const float*)d_in[9];
    const float* bih   = (const float*)d_in[11];
    const float* bhh   = (const float*)d_in[12];
    const float* ow    = (const float*)d_in[13];
    const float* ob    = (const float*)d_in[14];
    const int*   ei    = (const int*)d_in[15];
    float* out = (float*)d_out;

    cudaFuncSetAttribute(edge_kernel, cudaFuncAttributeMaxDynamicSharedMemorySize, EDGE_SMEM_BYTES);
    cudaFuncSetAttribute(node_kernel, cudaFuncAttributeMaxDynamicSharedMemorySize, NODE_SMEM_BYTES);
    cudaFuncSetAttribute(prep_kernel, cudaFuncAttributeMaxDynamicSharedMemorySize, PREP_SMEM_BYTES);

    zero_kernel<<<256, 256>>>();
    prep_kernel<<<NPRE + NYB + NWB, 256, PREP_SMEM_BYTES>>>(eattr, t, tw, tb, ei, x, w1, wih, ow);
    edge_kernel<<<148, 384, EDGE_SMEM_BYTES>>>(w1, b1, w2, b2, ei);
    node_kernel<<<148, 256, NODE_SMEM_BYTES>>>(bih, bhh, ob, out);
}

// round 16
// speedup vs baseline: 1.0769x; 1.0769x over previous
#include <cuda_runtime.h>
#include <cuda_bf16.h>
#include <cuda_fp16.h>
#include <math.h>
#include <stdint.h>

#define NN 50000
#define NE 800000
#define NODE_F 128
#define EDGE_F 32
#define TIME_D 16
#define K1 176
#define DN 128

typedef unsigned long long ull;

// ---------------- scratch ----------------
__device__ float g_agg[(size_t)NN * 128];
__device__ float g_cnt[NN];
__device__ uint32_t g_yf16[(size_t)NN * 64];        // Y = x @ W1x, f16x2, 4x4-block-permuted
__device__ uint32_t g_tfrag[(size_t)NE * 24];       // tail in fragment order [tile][p][lane]
__device__ uint32_t g_wf16[4 * 128 * 64];           // node weights f16x2: r, z, n, out

// ---------------- helpers ----------------
__device__ __forceinline__ uint32_t smem_u32(const void* p) {
    uint32_t a;
    asm("{ .reg .u64 t; cvta.to.shared.u64 t, %1; cvt.u32.u64 %0, t; }" : "=r"(a) : "l"(p));
    return a;
}
__device__ __forceinline__ float sigm(float x) { return 1.0f / (1.0f + expf(-x)); }

__device__ __forceinline__ uint32_t h2u(float a, float b) {
    __half2 h = __floats2half2_rn(a, b);
    return *reinterpret_cast<uint32_t*>(&h);
}

__device__ __forceinline__ void ldsm_x4(uint32_t& r0, uint32_t& r1, uint32_t& r2, uint32_t& r3,
                                        uint32_t addr) {
    asm volatile("ldmatrix.sync.aligned.m8n8.x4.shared.b16 {%0,%1,%2,%3}, [%4];"
                 : "=r"(r0), "=r"(r1), "=r"(r2), "=r"(r3) : "r"(addr));
}
__device__ __forceinline__ void mma_f16(float* d, const uint32_t* a, const uint32_t* b) {
    asm volatile("mma.sync.aligned.m16n8k16.row.col.f32.f16.f16.f32 "
                 "{%0,%1,%2,%3}, {%4,%5,%6,%7}, {%8,%9}, {%0,%1,%2,%3};"
                 : "+f"(d[0]), "+f"(d[1]), "+f"(d[2]), "+f"(d[3])
                 : "r"(a[0]), "r"(a[1]), "r"(a[2]), "r"(a[3]), "r"(b[0]), "r"(b[1]));
}
#define GBAR(id)    asm volatile("bar.sync %0, 128;" :: "r"(id) : "memory")

// ---------------- zero scratch ----------------
__global__ void zero_kernel() {
    int i = blockIdx.x * blockDim.x + threadIdx.x;
    int stride = gridDim.x * blockDim.x;
    float4 z = make_float4(0.f, 0.f, 0.f, 0.f);
    float4* a4 = reinterpret_cast<float4*>(g_agg);
    for (int j = i; j < NN * 128 / 4; j += stride) a4[j] = z;
    for (int j = i; j < NN; j += stride) g_cnt[j] = 0.f;
}

// ================= PREP KERNEL: edge-pre | Y-gemm | weight-convert =================
#define NPRE (NE / 256)            // 3125
#define NYB  ((NN + 63) / 64)      // 782
#define NWB  8
#define PREP_SMEM_BYTES 52352

#define YW 0          // [128][136] f16 = 34816
#define YA 34816      // [64][136]  f16 = 17408

__global__ __launch_bounds__(256)
void prep_kernel(const float* __restrict__ eattr, const float* __restrict__ tt,
                 const float* __restrict__ tw, const float* __restrict__ tb,
                 const int* __restrict__ ei, const float* __restrict__ x,
                 const float* __restrict__ w1, const float* __restrict__ wih,
                 const float* __restrict__ ow)
{
    extern __shared__ char smc[];
    const int b = blockIdx.x;
    const int tid = threadIdx.x;

    if (b < NPRE) {
        uint32_t* st = (uint32_t*)smc;     // [256][25]
        const int e = b * 256 + tid;

        uint32_t th[24];
        const float4* er = (const float4*)(eattr + (size_t)e * 32);
#pragma unroll
        for (int i = 0; i < 8; ++i) {
            float4 f = __ldg(&er[i]);
            th[2 * i]     = h2u(f.x, f.y);
            th[2 * i + 1] = h2u(f.z, f.w);
        }
        float tv = __ldg(&tt[e]);
#pragma unroll
        for (int d = 0; d < 8; ++d) {
            float a = cosf(tv * __ldg(&tw[2 * d])     + __ldg(&tb[2 * d]));
            float bb = cosf(tv * __ldg(&tw[2 * d + 1]) + __ldg(&tb[2 * d + 1]));
            th[16 + d] = h2u(a, bb);
        }
#pragma unroll
        for (int j = 0; j < 24; ++j) st[tid * 25 + j] = th[j];
        atomicAdd(&g_cnt[__ldg(&ei[NE + e])], 1.0f);
        __syncthreads();

        const int tl = tid >> 5, L = tid & 31;
        uint32_t* dst = g_tfrag + ((size_t)b * 8 + tl) * 768 + L;
#pragma unroll
        for (int p = 0; p < 24; ++p) {
            const int mfks = p >> 2, rsel = p & 3;
            const int mf = mfks / 3, ks = mfks - mf * 3;
            const int esel = rsel & 1, part = rsel >> 1;
            const int r = mf * 16 + esel * 8 + (L >> 2);
            const int j = ks * 8 + part * 4 + (L & 3);
            dst[p * 32] = st[(tl * 32 + r) * 25 + j];
        }
    } else if (b < NPRE + NYB) {
        const uint32_t smb = smem_u32(smc);
        const int wid = tid >> 5, lane = tid & 31;
        const int m0 = (wid & 3) * 16, nbase = (wid >> 2) * 64;
        const int base = (b - NPRE) * 64;
        const int crow = lane >> 2, ccol = (lane & 3) * 2;

        for (int idx = tid; idx < 128 * 128; idx += 256) {
            int k = idx >> 7, n = idx & 127;
            *(__half*)(smc + YW + 2 * (n * 136 + k)) = __float2half_rn(w1[k * 128 + n]);
        }
        for (int idx = tid; idx < 64 * 64; idx += 256) {
            int m = idx >> 6, kp = idx & 63;
            int row = base + m;
            uint32_t v = 0u;
            if (row < NN)
                v = h2u(__ldg(&x[(size_t)row * 128 + 2 * kp]),
                        __ldg(&x[(size_t)row * 128 + 2 * kp + 1]));
            *(uint32_t*)(smc + YA + 2 * (m * 136 + 2 * kp)) = v;
        }
        __syncthreads();

        const uint32_t aRow = (uint32_t)((m0 + (lane & 15)) * 136 + ((lane >> 4) << 3)) * 2;
        const uint32_t bRow = (uint32_t)((lane & 7) + ((lane >> 4) << 3));
        const uint32_t bLane = (uint32_t)(bRow * 136 + (((lane >> 3) & 1) << 3)) * 2;

        float acc[8][4];
#pragma unroll
        for (int j = 0; j < 8; ++j)
#pragma unroll
            for (int q = 0; q < 4; ++q) acc[j][q] = 0.f;

#pragma unroll
        for (int ks = 0; ks < 8; ++ks) {
            const uint32_t kOff = (uint32_t)(ks * 16) * 2;
            uint32_t a[4];
            ldsm_x4(a[0], a[1], a[2], a[3], smb + YA + aRow + kOff);
#pragma unroll
            for (int jj = 0; jj < 4; ++jj) {
                const uint32_t nOff = (uint32_t)((nbase + jj * 16) * 136) * 2;
                uint32_t bb[4];
                ldsm_x4(bb[0], bb[1], bb[2], bb[3], smb + YW + bLane + nOff + kOff);
                mma_f16(acc[2 * jj],     a, bb);
                mma_f16(acc[2 * jj + 1], a, bb + 2);
            }
        }

        int r0 = m0 + crow, r1 = r0 + 8;
        int nd0 = base + r0, nd1 = base + r1;
#pragma unroll
        for (int j = 0; j < 8; ++j) {
            int c = (nbase + j * 8 + ccol) >> 1;
            int p = (c & ~15) | ((c & 3) << 2) | ((c >> 2) & 3);   // 4x4 block transpose
            if (nd0 < NN) g_yf16[(size_t)nd0 * 64 + p] = h2u(acc[j][0], acc[j][1]);
            if (nd1 < NN) g_yf16[(size_t)nd1 * 64 + p] = h2u(acc[j][2], acc[j][3]);
        }
    } else {
        const int wb = b - NPRE - NYB;       // 0..7
#pragma unroll
        for (int it = 0; it < 16; ++it) {
            int i = wb * 4096 + it * 256 + tid;
            int mat = i >> 13;
            int r = (i >> 6) & 127;
            int kp = i & 63;
            const float* src = (mat < 3) ? (wih + mat * 16384) : ow;
            g_wf16[i] = h2u(__ldg(&src[r * 128 + 2 * kp]), __ldg(&src[r * 128 + 2 * kp + 1]));
        }
    }
}

// ================= EDGE KERNEL (R14 + src/tgt prefetch) =================
#define EK_M   32
#define NT32   (NE / EK_M)
#define NGRP   3
#define LDAT   56
#define LDH    136

#define SM_W1T 0
#define SM_W2  14336
#define SM_H   49152
#define SM_B1  75264
#define SM_B2  75776
#define EDGE_SMEM_BYTES 76288

__global__ __launch_bounds__(384, 1)
void edge_kernel(const float* __restrict__ w1, const float* __restrict__ b1,
                 const float* __restrict__ w2, const float* __restrict__ b2,
                 const int* __restrict__ ei)
{
    extern __shared__ char smc[];
    const uint32_t smb = smem_u32(smc);
    const int tid = threadIdx.x;
    const int wid = tid >> 5, lane = tid & 31;
    const int grp = wid >> 2;
    const int gw = wid & 3;
    const int nbase = gw * 32;

    float* b1s = (float*)(smc + SM_B1);
    float* b2s = (float*)(smc + SM_B2);

    for (int idx = tid; idx < 48 * DN; idx += 384) {
        int k = idx >> 7, n = idx & 127;
        *(__half*)(smc + SM_W1T + 2 * (n * LDAT + k)) = __float2half_rn(w1[(128 + k) * 128 + n]);
    }
    for (int idx = tid; idx < DN * DN; idx += 384) {
        int k = idx >> 7, n = idx & 127;
        *(__half*)(smc + SM_W2 + 2 * (n * LDH + k)) = __float2half_rn(w2[idx]);
    }
    for (int i = tid; i < 128; i += 384) { b1s[i] = b1[i]; b2s[i] = b2[i]; }
    __syncthreads();

    const int barId = 1 + grp;
    const uint32_t hBase = smb + SM_H + grp * 8704;

    const uint32_t hRow0 = (uint32_t)((lane & 15) * LDH + ((lane >> 4) << 3)) * 2;
    const uint32_t hRow1 = hRow0 + (uint32_t)(16 * LDH) * 2;
    const uint32_t bRow = (uint32_t)((lane & 7) + ((lane >> 4) << 3));
    const uint32_t bColPiece = (uint32_t)(((lane >> 3) & 1) << 3);
    const uint32_t b1LaneOff = (uint32_t)(bRow * LDAT + bColPiece) * 2;
    const uint32_t b2LaneOff = (uint32_t)(bRow * LDH + bColPiece) * 2;
    const int crow = lane >> 2;
    const int ccol = (lane & 3) * 2;
    const int yoff = gw * 16 + (lane & 3) * 4;

    uint32_t w1f[24];
#pragma unroll
    for (int ks = 0; ks < 3; ++ks)
#pragma unroll
        for (int jj = 0; jj < 2; ++jj)
            ldsm_x4(w1f[(ks * 2 + jj) * 4], w1f[(ks * 2 + jj) * 4 + 1],
                    w1f[(ks * 2 + jj) * 4 + 2], w1f[(ks * 2 + jj) * 4 + 3],
                    smb + SM_W1T + b1LaneOff + (uint32_t)((nbase + jj * 16) * LDAT) * 2
                    + (uint32_t)(ks * 32));

    int tile = blockIdx.x * NGRP + grp;
    const int step = gridDim.x * NGRP;

    uint32_t tailA[24], tailN[24];
    int s00, s01, s10, s11, t00, t01, t10, t11;
    if (tile < NT32) {
        const uint32_t* tf = g_tfrag + (size_t)tile * 768 + lane;
#pragma unroll
        for (int p = 0; p < 24; ++p) tailA[p] = __ldg(&tf[p * 32]);
        const int ebase = tile * EK_M;
        s00 = __ldg(&ei[ebase + crow]);
        s01 = __ldg(&ei[ebase + crow + 8]);
        s10 = __ldg(&ei[ebase + 16 + crow]);
        s11 = __ldg(&ei[ebase + 24 + crow]);
        t00 = __ldg(&ei[NE + ebase + crow]);
        t01 = __ldg(&ei[NE + ebase + crow + 8]);
        t10 = __ldg(&ei[NE + ebase + 16 + crow]);
        t11 = __ldg(&ei[NE + ebase + 24 + crow]);
    }

    for (; tile < NT32; tile += step) {
        // ---- Y gather: src indices already resident ----
        uint4 Y4[4];
        Y4[0] = __ldg((const uint4*)&g_yf16[(size_t)s00 * 64 + yoff]);
        Y4[1] = __ldg((const uint4*)&g_yf16[(size_t)s01 * 64 + yoff]);
        Y4[2] = __ldg((const uint4*)&g_yf16[(size_t)s10 * 64 + yoff]);
        Y4[3] = __ldg((const uint4*)&g_yf16[(size_t)s11 * 64 + yoff]);
        const int ct00 = t00, ct01 = t01, ct10 = t10, ct11 = t11;

        float acc[2][4][4];
#pragma unroll
        for (int i = 0; i < 2; ++i)
#pragma unroll
            for (int j = 0; j < 4; ++j)
#pragma unroll
                for (int q = 0; q < 4; ++q) acc[i][j][q] = 0.f;

        // ---------- GEMM1': tail[32,48] @ W1t ----------
#pragma unroll
        for (int ks = 0; ks < 3; ++ks) {
#pragma unroll
            for (int jj = 0; jj < 2; ++jj) {
                const uint32_t* b = &w1f[(ks * 2 + jj) * 4];
                mma_f16(acc[0][jj * 2],     &tailA[(0 * 3 + ks) * 4], b);
                mma_f16(acc[0][jj * 2 + 1], &tailA[(0 * 3 + ks) * 4], b + 2);
                mma_f16(acc[1][jj * 2],     &tailA[(1 * 3 + ks) * 4], b);
                mma_f16(acc[1][jj * 2 + 1], &tailA[(1 * 3 + ks) * 4], b + 2);
            }
        }

        // ---- prefetch next tile's tail frags + indices ----
        {
            const int nxt = tile + step;
            if (nxt < NT32) {
                const uint32_t* tf = g_tfrag + (size_t)nxt * 768 + lane;
#pragma unroll
                for (int p = 0; p < 24; ++p) tailN[p] = __ldg(&tf[p * 32]);
                const int nb = nxt * EK_M;
                s00 = __ldg(&ei[nb + crow]);
                s01 = __ldg(&ei[nb + crow + 8]);
                s10 = __ldg(&ei[nb + 16 + crow]);
                s11 = __ldg(&ei[nb + 24 + crow]);
                t00 = __ldg(&ei[NE + nb + crow]);
                t01 = __ldg(&ei[NE + nb + crow + 8]);
                t10 = __ldg(&ei[NE + nb + 16 + crow]);
                t11 = __ldg(&ei[NE + nb + 24 + crow]);
            }
        }

        // ---------- epilogue 1: relu(acc + Y + b1) -> H (f16) ----------
#pragma unroll
        for (int mf = 0; mf < 2; ++mf) {
            int r0 = mf * 16 + crow, r1 = r0 + 8;
#pragma unroll
            for (int j = 0; j < 4; ++j) {
                int n = nbase + j * 8 + ccol;
                uint32_t yu0 = ((const uint32_t*)&Y4[mf * 2 + 0])[j];
                uint32_t yu1 = ((const uint32_t*)&Y4[mf * 2 + 1])[j];
                __half2 y0 = *reinterpret_cast<__half2*>(&yu0);
                __half2 y1 = *reinterpret_cast<__half2*>(&yu1);
                float v0 = fmaxf(acc[mf][j][0] + __low2float(y0)  + b1s[n],     0.f);
                float v1 = fmaxf(acc[mf][j][1] + __high2float(y0) + b1s[n + 1], 0.f);
                float v2 = fmaxf(acc[mf][j][2] + __low2float(y1)  + b1s[n],     0.f);
                float v3 = fmaxf(acc[mf][j][3] + __high2float(y1) + b1s[n + 1], 0.f);
                *(__half2*)(smc + (hBase - smb) + 2 * (r0 * LDH + n)) = __floats2half2_rn(v0, v1);
                *(__half2*)(smc + (hBase - smb) + 2 * (r1 * LDH + n)) = __floats2half2_rn(v2, v3);
            }
        }
        GBAR(barId);

        // ---------- GEMM2: D2 = H(128) @ W2 ----------
#pragma unroll
        for (int i = 0; i < 2; ++i)
#pragma unroll
            for (int j = 0; j < 4; ++j)
#pragma unroll
                for (int q = 0; q < 4; ++q) acc[i][j][q] = 0.f;

#pragma unroll
        for (int ks = 0; ks < 8; ++ks) {
            const uint32_t kOff = (uint32_t)(ks * 16) * 2;
            uint32_t a0[4], a1[4];
            ldsm_x4(a0[0], a0[1], a0[2], a0[3], hBase + hRow0 + kOff);
            ldsm_x4(a1[0], a1[1], a1[2], a1[3], hBase + hRow1 + kOff);
#pragma unroll
            for (int jj = 0; jj < 2; ++jj) {
                const uint32_t nOff = (uint32_t)((nbase + jj * 16) * LDH) * 2;
                uint32_t b[4];
                ldsm_x4(b[0], b[1], b[2], b[3], smb + SM_W2 + b2LaneOff + nOff + kOff);
                mma_f16(acc[0][jj * 2],     a0, b);
                mma_f16(acc[0][jj * 2 + 1], a0, b + 2);
                mma_f16(acc[1][jj * 2],     a1, b);
                mma_f16(acc[1][jj * 2 + 1], a1, b + 2);
            }
        }

        // ---------- epilogue 2: scatter ----------
#pragma unroll
        for (int mf = 0; mf < 2; ++mf) {
            int tg0 = (mf == 0) ? ct00 : ct10;
            int tg1 = (mf == 0) ? ct01 : ct11;
            size_t ga0 = __cvta_generic_to_global(&g_agg[(size_t)tg0 * 128]);
            size_t ga1 = __cvta_generic_to_global(&g_agg[(size_t)tg1 * 128]);
#pragma unroll
            for (int j = 0; j < 4; ++j) {
                int n = nbase + j * 8 + ccol;
                float v0 = acc[mf][j][0] + b2s[n];
                float v1 = acc[mf][j][1] + b2s[n + 1];
                float v2 = acc[mf][j][2] + b2s[n];
                float v3 = acc[mf][j][3] + b2s[n + 1];
                asm volatile("red.global.add.v2.f32 [%0], {%1,%2};"
                             :: "l"(ga0 + (size_t)n * 4), "f"(v0), "f"(v1) : "memory");
                asm volatile("red.global.add.v2.f32 [%0], {%1,%2};"
                             :: "l"(ga1 + (size_t)n * 4), "f"(v2), "f"(v3) : "memory");
            }
        }
        GBAR(barId);

#pragma unroll
        for (int i = 0; i < 24; ++i) tailA[i] = tailN[i];
    }
}

// ================= NODE KERNEL (2 weights resident, 2 CTAs/SM) =================
#define NLDB 136
#define NW0  0        // slot0: 34816
#define NW1  34816    // slot1: 34816
#define NVS  69632    // [64][136] f16 = 17408
#define NMS  87040    // 17408
#define NODE_SMEM_BYTES 104448

__device__ __forceinline__ void hgemm1_128(uint32_t bBase, uint32_t aAddr,
                                           int nbase, float acc[8][4]) {
#pragma unroll
    for (int j = 0; j < 8; ++j)
#pragma unroll
        for (int q = 0; q < 4; ++q) acc[j][q] = 0.f;
#pragma unroll
    for (int ks = 0; ks < 8; ++ks) {
        const uint32_t kOff = (uint32_t)(ks * 16) * 2;
        uint32_t a[4];
        ldsm_x4(a[0], a[1], a[2], a[3], aAddr + kOff);
#pragma unroll
        for (int jj = 0; jj < 4; ++jj) {
            const uint32_t nOff = (uint32_t)((nbase + jj * 16) * NLDB) * 2;
            uint32_t b[4];
            ldsm_x4(b[0], b[1], b[2], b[3], bBase + nOff + kOff);
            mma_f16(acc[2 * jj],     a, b);
            mma_f16(acc[2 * jj + 1], a, b + 2);
        }
    }
}

// stage preconverted f16 weights: mat 0=r,1=z,2=n,3=out into smem slot
__device__ __forceinline__ void node_stageW(char* smc, int slot, int mat, int tid) {
    const uint4* src = (const uint4*)(g_wf16 + mat * 8192);
    char* dst = smc + (slot ? NW1 : NW0);
    for (int idx = tid; idx < 128 * 16; idx += 256) {
        int n = idx >> 4, g = idx & 15;
        uint4 v = __ldg(&src[idx]);
        *(uint4*)(dst + n * (NLDB * 2) + g * 16) = v;
    }
}

__global__ __launch_bounds__(256, 2)
void node_kernel(const float* __restrict__ bih, const float* __restrict__ bhh,
                 const float* __restrict__ ob, float* __restrict__ out)
{
    extern __shared__ char smc[];
    const uint32_t smb = smem_u32(smc);
    const int tid = threadIdx.x, wid = tid >> 5, lane = tid & 31;
    const int m0 = (wid & 3) * 16, nbase = (wid >> 2) * 64;
    const int base = blockIdx.x * 64;
    const int crow = lane >> 2, ccol = (lane & 3) * 2;

    // ---- stage Wr, Wn + V tile ----
    node_stageW(smc, 0, 0, tid);       // r -> slot0
    node_stageW(smc, 1, 2, tid);       // n -> slot1
    for (int idx = tid; idx < 64 * 64; idx += 256) {
        int m = idx >> 6, kp = idx & 63;
        int nd = base + m;
        float a0 = 0.f, a1 = 0.f;
        if (nd < NN) {
            float inv = 1.0f / fmaxf(g_cnt[nd], 1.0f);
            a0 = g_agg[(size_t)nd * 128 + 2 * kp] * inv;
            a1 = g_agg[(size_t)nd * 128 + 2 * kp + 1] * inv;
        }
        *(uint32_t*)(smc + NVS + 2 * (m * NLDB + 2 * kp)) = h2u(a0, a1);
    }
    __syncthreads();

    const uint32_t aRow = (uint32_t)((m0 + (lane & 15)) * NLDB + ((lane >> 4) << 3)) * 2;
    const uint32_t bRow = (uint32_t)((lane & 7) + ((lane >> 4) << 3));
    const uint32_t bLane = (uint32_t)(bRow * NLDB + (((lane >> 3) & 1) << 3)) * 2;

    float acc[8][4], rg[8][4], ng[8][4];

    // ---- r gate (slot0) + n gate (slot1), no sync between ----
    hgemm1_128(smb + NW0 + bLane, smb + NVS + aRow, nbase, acc);
#pragma unroll
    for (int j = 0; j < 8; ++j) {
        int n = nbase + j * 8 + ccol;
        rg[j][0] = sigm(acc[j][0] + __ldg(&bih[n])     + __ldg(&bhh[n]));
        rg[j][1] = sigm(acc[j][1] + __ldg(&bih[n + 1]) + __ldg(&bhh[n + 1]));
        rg[j][2] = sigm(acc[j][2] + __ldg(&bih[n])     + __ldg(&bhh[n]));
        rg[j][3] = sigm(acc[j][3] + __ldg(&bih[n + 1]) + __ldg(&bhh[n + 1]));
    }

    hgemm1_128(smb + NW1 + bLane, smb + NVS + aRow, nbase, acc);
#pragma unroll
    for (int j = 0; j < 8; ++j) {
        int n = 256 + nbase + j * 8 + ccol;
        ng[j][0] = tanhf(acc[j][0] + __ldg(&bih[n])     + rg[j][0] * __ldg(&bhh[n]));
        ng[j][1] = tanhf(acc[j][1] + __ldg(&bih[n + 1]) + rg[j][1] * __ldg(&bhh[n + 1]));
        ng[j][2] = tanhf(acc[j][2] + __ldg(&bih[n])     + rg[j][2] * __ldg(&bhh[n]));
        ng[j][3] = tanhf(acc[j][3] + __ldg(&bih[n + 1]) + rg[j][3] * __ldg(&bhh[n + 1]));
    }
    __syncthreads();

    // ---- stage Wz, Wo ----
    node_stageW(smc, 0, 1, tid);       // z -> slot0
    node_stageW(smc, 1, 3, tid);       // out -> slot1
    __syncthreads();

    // ---- z gate + memory = (1-z)*n -> Ms ----
    hgemm1_128(smb + NW0 + bLane, smb + NVS + aRow, nbase, acc);
    {
        int r0 = m0 + crow, r1 = m0 + crow + 8;
#pragma unroll
        for (int j = 0; j < 8; ++j) {
            int nl = nbase + j * 8 + ccol;
            int n = 128 + nl;
            float z0 = sigm(acc[j][0] + __ldg(&bih[n])     + __ldg(&bhh[n]));
            float z1 = sigm(acc[j][1] + __ldg(&bih[n + 1]) + __ldg(&bhh[n + 1]));
            float z2 = sigm(acc[j][2] + __ldg(&bih[n])     + __ldg(&bhh[n]));
            float z3 = sigm(acc[j][3] + __ldg(&bih[n + 1]) + __ldg(&bhh[n + 1]));
            *(uint32_t*)(smc + NMS + 2 * (r0 * NLDB + nl)) =
                h2u((1.f - z0) * ng[j][0], (1.f - z1) * ng[j][1]);
            *(uint32_t*)(smc + NMS + 2 * (r1 * NLDB + nl)) =
                h2u((1.f - z2) * ng[j][2], (1.f - z3) * ng[j][3]);
        }
    }
    __syncthreads();

    // ---- out projection (slot1) ----
    hgemm1_128(smb + NW1 + bLane, smb + NMS + aRow, nbase, acc);
    {
        int r0 = m0 + crow, r1 = m0 + crow + 8;
        int nd0 = base + r0, nd1 = base + r1;
#pragma unroll
        for (int j = 0; j < 8; ++j) {
            int n = nbase + j * 8 + ccol;
            float o0 = __ldg(&ob[n]), o1 = __ldg(&ob[n + 1]);
            if (nd0 < NN)
                *(float2*)&out[(size_t)nd0 * 128 + n] = make_float2(acc[j][0] + o0, acc[j][1] + o1);
            if (nd1 < NN)
                *(float2*)&out[(size_t)nd1 * 128 + n] = make_float2(acc[j][2] + o0, acc[j][3] + o1);
        }
    }
}

// ================= launch =================
extern "C" void kernel_launch(void* const* d_in, const int* in_sizes, int n_in,
                              void* d_out, int out_size) {
    const float* x     = (const float*)d_in[0];
    const float* eattr = (const float*)d_in[1];
    const float* t     = (const float*)d_in[2];
    const float* tw    = (const float*)d_in[3];
    const float* tb    = (const float*)d_in[4];
    const float* w1    = (const float*)d_in[5];
    const float* b1    = (const float*)d_in[6];
    const float* w2    = (const float*)d_in[7];
    const float* b2    = (const float*)d_in[8];
    const float* wih   = (const float*)d_in[9];
    const float* bih   = (const float*)d_in[11];
    const float* bhh   = (const float*)d_in[12];
    const float* ow    = (const float*)d_in[13];
    const float* ob    = (const float*)d_in[14];
    const int*   ei    = (const int*)d_in[15];
    float* out = (float*)d_out;

    cudaFuncSetAttribute(edge_kernel, cudaFuncAttributeMaxDynamicSharedMemorySize, EDGE_SMEM_BYTES);
    cudaFuncSetAttribute(node_kernel, cudaFuncAttributeMaxDynamicSharedMemorySize, NODE_SMEM_BYTES);
    cudaFuncSetAttribute(prep_kernel, cudaFuncAttributeMaxDynamicSharedMemorySize, PREP_SMEM_BYTES);

    zero_kernel<<<256, 256>>>();
    prep_kernel<<<NPRE + NYB + NWB, 256, PREP_SMEM_BYTES>>>(eattr, t, tw, tb, ei, x, w1, wih, ow);
    edge_kernel<<<148, 384, EDGE_SMEM_BYTES>>>(w1, b1, w2, b2, ei);
    node_kernel<<<(NN + 63) / 64, 256, NODE_SMEM_BYTES>>>(bih, bhh, ob, out);
}

// round 17
// speedup vs baseline: 1.1023x; 1.0236x over previous
#include <cuda_runtime.h>
#include <cuda_bf16.h>
#include <cuda_fp16.h>
#include <math.h>
#include <stdint.h>

#define NN 50000
#define NE 800000
#define NODE_F 128
#define EDGE_F 32
#define TIME_D 16
#define K1 176
#define DN 128

typedef unsigned long long ull;

// ---------------- scratch ----------------
__device__ float g_agg[(size_t)NN * 128];
__device__ float g_cnt[NN];
__device__ uint32_t g_yf16[(size_t)NN * 64];        // Y = x @ W1x, f16x2, 4x4-block-permuted
__device__ uint32_t g_tfrag[(size_t)NE * 24];       // tail in fragment order [tile][p][lane]
__device__ uint32_t g_wf16[4 * 128 * 64];           // node weights f16x2: r, z, n, out

// ---------------- helpers ----------------
__device__ __forceinline__ uint32_t smem_u32(const void* p) {
    uint32_t a;
    asm("{ .reg .u64 t; cvta.to.shared.u64 t, %1; cvt.u32.u64 %0, t; }" : "=r"(a) : "l"(p));
    return a;
}
__device__ __forceinline__ float sigm(float x) { return 1.0f / (1.0f + expf(-x)); }

__device__ __forceinline__ uint32_t h2u(float a, float b) {
    __half2 h = __floats2half2_rn(a, b);
    return *reinterpret_cast<uint32_t*>(&h);
}

__device__ __forceinline__ void ldsm_x4(uint32_t& r0, uint32_t& r1, uint32_t& r2, uint32_t& r3,
                                        uint32_t addr) {
    asm volatile("ldmatrix.sync.aligned.m8n8.x4.shared.b16 {%0,%1,%2,%3}, [%4];"
                 : "=r"(r0), "=r"(r1), "=r"(r2), "=r"(r3) : "r"(addr));
}
__device__ __forceinline__ void mma_f16(float* d, const uint32_t* a, const uint32_t* b) {
    asm volatile("mma.sync.aligned.m16n8k16.row.col.f32.f16.f16.f32 "
                 "{%0,%1,%2,%3}, {%4,%5,%6,%7}, {%8,%9}, {%0,%1,%2,%3};"
                 : "+f"(d[0]), "+f"(d[1]), "+f"(d[2]), "+f"(d[3])
                 : "r"(a[0]), "r"(a[1]), "r"(a[2]), "r"(a[3]), "r"(b[0]), "r"(b[1]));
}
#define GBAR(id)    asm volatile("bar.sync %0, 128;" :: "r"(id) : "memory")

// ---------------- zero scratch ----------------
__global__ void zero_kernel() {
    int i = blockIdx.x * blockDim.x + threadIdx.x;
    int stride = gridDim.x * blockDim.x;
    float4 z = make_float4(0.f, 0.f, 0.f, 0.f);
    float4* a4 = reinterpret_cast<float4*>(g_agg);
    for (int j = i; j < NN * 128 / 4; j += stride) a4[j] = z;
    for (int j = i; j < NN; j += stride) g_cnt[j] = 0.f;
}

// ================= PREP KERNEL: edge-pre | Y-gemm | weight-convert =================
#define NPRE (NE / 256)            // 3125
#define NYB  ((NN + 63) / 64)      // 782
#define NWB  8
#define PREP_SMEM_BYTES 52352

#define YW 0          // [128][136] f16 = 34816
#define YA 34816      // [64][136]  f16 = 17408

__global__ __launch_bounds__(256)
void prep_kernel(const float* __restrict__ eattr, const float* __restrict__ tt,
                 const float* __restrict__ tw, const float* __restrict__ tb,
                 const int* __restrict__ ei, const float* __restrict__ x,
                 const float* __restrict__ w1, const float* __restrict__ wih,
                 const float* __restrict__ ow)
{
    extern __shared__ char smc[];
    const int b = blockIdx.x;
    const int tid = threadIdx.x;

    if (b < NPRE) {
        uint32_t* st = (uint32_t*)smc;     // [256][25]
        const int e = b * 256 + tid;

        uint32_t th[24];
        const float4* er = (const float4*)(eattr + (size_t)e * 32);
#pragma unroll
        for (int i = 0; i < 8; ++i) {
            float4 f = __ldg(&er[i]);
            th[2 * i]     = h2u(f.x, f.y);
            th[2 * i + 1] = h2u(f.z, f.w);
        }
        float tv = __ldg(&tt[e]);
#pragma unroll
        for (int d = 0; d < 8; ++d) {
            float a = cosf(tv * __ldg(&tw[2 * d])     + __ldg(&tb[2 * d]));
            float bb = cosf(tv * __ldg(&tw[2 * d + 1]) + __ldg(&tb[2 * d + 1]));
            th[16 + d] = h2u(a, bb);
        }
#pragma unroll
        for (int j = 0; j < 24; ++j) st[tid * 25 + j] = th[j];
        atomicAdd(&g_cnt[__ldg(&ei[NE + e])], 1.0f);
        __syncthreads();

        const int tl = tid >> 5, L = tid & 31;
        uint32_t* dst = g_tfrag + ((size_t)b * 8 + tl) * 768 + L;
#pragma unroll
        for (int p = 0; p < 24; ++p) {
            const int mfks = p >> 2, rsel = p & 3;
            const int mf = mfks / 3, ks = mfks - mf * 3;
            const int esel = rsel & 1, part = rsel >> 1;
            const int r = mf * 16 + esel * 8 + (L >> 2);
            const int j = ks * 8 + part * 4 + (L & 3);
            dst[p * 32] = st[(tl * 32 + r) * 25 + j];
        }
    } else if (b < NPRE + NYB) {
        const uint32_t smb = smem_u32(smc);
        const int wid = tid >> 5, lane = tid & 31;
        const int m0 = (wid & 3) * 16, nbase = (wid >> 2) * 64;
        const int base = (b - NPRE) * 64;
        const int crow = lane >> 2, ccol = (lane & 3) * 2;

        for (int idx = tid; idx < 128 * 128; idx += 256) {
            int k = idx >> 7, n = idx & 127;
            *(__half*)(smc + YW + 2 * (n * 136 + k)) = __float2half_rn(w1[k * 128 + n]);
        }
        for (int idx = tid; idx < 64 * 64; idx += 256) {
            int m = idx >> 6, kp = idx & 63;
            int row = base + m;
            uint32_t v = 0u;
            if (row < NN)
                v = h2u(__ldg(&x[(size_t)row * 128 + 2 * kp]),
                        __ldg(&x[(size_t)row * 128 + 2 * kp + 1]));
            *(uint32_t*)(smc + YA + 2 * (m * 136 + 2 * kp)) = v;
        }
        __syncthreads();

        const uint32_t aRow = (uint32_t)((m0 + (lane & 15)) * 136 + ((lane >> 4) << 3)) * 2;
        const uint32_t bRow = (uint32_t)((lane & 7) + ((lane >> 4) << 3));
        const uint32_t bLane = (uint32_t)(bRow * 136 + (((lane >> 3) & 1) << 3)) * 2;

        float acc[8][4];
#pragma unroll
        for (int j = 0; j < 8; ++j)
#pragma unroll
            for (int q = 0; q < 4; ++q) acc[j][q] = 0.f;

#pragma unroll
        for (int ks = 0; ks < 8; ++ks) {
            const uint32_t kOff = (uint32_t)(ks * 16) * 2;
            uint32_t a[4];
            ldsm_x4(a[0], a[1], a[2], a[3], smb + YA + aRow + kOff);
#pragma unroll
            for (int jj = 0; jj < 4; ++jj) {
                const uint32_t nOff = (uint32_t)((nbase + jj * 16) * 136) * 2;
                uint32_t bb[4];
                ldsm_x4(bb[0], bb[1], bb[2], bb[3], smb + YW + bLane + nOff + kOff);
                mma_f16(acc[2 * jj],     a, bb);
                mma_f16(acc[2 * jj + 1], a, bb + 2);
            }
        }

        int r0 = m0 + crow, r1 = r0 + 8;
        int nd0 = base + r0, nd1 = base + r1;
#pragma unroll
        for (int j = 0; j < 8; ++j) {
            int c = (nbase + j * 8 + ccol) >> 1;
            int p = (c & ~15) | ((c & 3) << 2) | ((c >> 2) & 3);   // 4x4 block transpose
            if (nd0 < NN) g_yf16[(size_t)nd0 * 64 + p] = h2u(acc[j][0], acc[j][1]);
            if (nd1 < NN) g_yf16[(size_t)nd1 * 64 + p] = h2u(acc[j][2], acc[j][3]);
        }
    } else {
        const int wb = b - NPRE - NYB;       // 0..7
#pragma unroll
        for (int it = 0; it < 16; ++it) {
            int i = wb * 4096 + it * 256 + tid;
            int mat = i >> 13;
            int r = (i >> 6) & 127;
            int kp = i & 63;
            const float* src = (mat < 3) ? (wih + mat * 16384) : ow;
            g_wf16[i] = h2u(__ldg(&src[r * 128 + 2 * kp]), __ldg(&src[r * 128 + 2 * kp + 1]));
        }
    }
}

// ================= EDGE KERNEL (R16 + shuffle-paired red.v4 scatter) =================
#define EK_M   32
#define NT32   (NE / EK_M)
#define NGRP   3
#define LDAT   56
#define LDH    136

#define SM_W1T 0
#define SM_W2  14336
#define SM_H   49152
#define SM_B1  75264
#define SM_B2  75776
#define EDGE_SMEM_BYTES 76288

__global__ __launch_bounds__(384, 1)
void edge_kernel(const float* __restrict__ w1, const float* __restrict__ b1,
                 const float* __restrict__ w2, const float* __restrict__ b2,
                 const int* __restrict__ ei)
{
    extern __shared__ char smc[];
    const uint32_t smb = smem_u32(smc);
    const int tid = threadIdx.x;
    const int wid = tid >> 5, lane = tid & 31;
    const int grp = wid >> 2;
    const int gw = wid & 3;
    const int nbase = gw * 32;

    float* b1s = (float*)(smc + SM_B1);
    float* b2s = (float*)(smc + SM_B2);

    for (int idx = tid; idx < 48 * DN; idx += 384) {
        int k = idx >> 7, n = idx & 127;
        *(__half*)(smc + SM_W1T + 2 * (n * LDAT + k)) = __float2half_rn(w1[(128 + k) * 128 + n]);
    }
    for (int idx = tid; idx < DN * DN; idx += 384) {
        int k = idx >> 7, n = idx & 127;
        *(__half*)(smc + SM_W2 + 2 * (n * LDH + k)) = __float2half_rn(w2[idx]);
    }
    for (int i = tid; i < 128; i += 384) { b1s[i] = b1[i]; b2s[i] = b2[i]; }
    __syncthreads();

    const int barId = 1 + grp;
    const uint32_t hBase = smb + SM_H + grp * 8704;

    const uint32_t hRow0 = (uint32_t)((lane & 15) * LDH + ((lane >> 4) << 3)) * 2;
    const uint32_t hRow1 = hRow0 + (uint32_t)(16 * LDH) * 2;
    const uint32_t bRow = (uint32_t)((lane & 7) + ((lane >> 4) << 3));
    const uint32_t bColPiece = (uint32_t)(((lane >> 3) & 1) << 3);
    const uint32_t b1LaneOff = (uint32_t)(bRow * LDAT + bColPiece) * 2;
    const uint32_t b2LaneOff = (uint32_t)(bRow * LDH + bColPiece) * 2;
    const int crow = lane >> 2;
    const int ccol = (lane & 3) * 2;
    const int yoff = gw * 16 + (lane & 3) * 4;
    const int evenLane = !(lane & 1);
    const int ccolE = (lane & 2) * 2;      // pair-base column (even lane's ccol)

    uint32_t w1f[24];
#pragma unroll
    for (int ks = 0; ks < 3; ++ks)
#pragma unroll
        for (int jj = 0; jj < 2; ++jj)
            ldsm_x4(w1f[(ks * 2 + jj) * 4], w1f[(ks * 2 + jj) * 4 + 1],
                    w1f[(ks * 2 + jj) * 4 + 2], w1f[(ks * 2 + jj) * 4 + 3],
                    smb + SM_W1T + b1LaneOff + (uint32_t)((nbase + jj * 16) * LDAT) * 2
                    + (uint32_t)(ks * 32));

    int tile = blockIdx.x * NGRP + grp;
    const int step = gridDim.x * NGRP;

    uint32_t tailA[24], tailN[24];
    int s00, s01, s10, s11, t00, t01, t10, t11;
    if (tile < NT32) {
        const uint32_t* tf = g_tfrag + (size_t)tile * 768 + lane;
#pragma unroll
        for (int p = 0; p < 24; ++p) tailA[p] = __ldg(&tf[p * 32]);
        const int ebase = tile * EK_M;
        s00 = __ldg(&ei[ebase + crow]);
        s01 = __ldg(&ei[ebase + crow + 8]);
        s10 = __ldg(&ei[ebase + 16 + crow]);
        s11 = __ldg(&ei[ebase + 24 + crow]);
        t00 = __ldg(&ei[NE + ebase + crow]);
        t01 = __ldg(&ei[NE + ebase + crow + 8]);
        t10 = __ldg(&ei[NE + ebase + 16 + crow]);
        t11 = __ldg(&ei[NE + ebase + 24 + crow]);
    }

    for (; tile < NT32; tile += step) {
        uint4 Y4[4];
        Y4[0] = __ldg((const uint4*)&g_yf16[(size_t)s00 * 64 + yoff]);
        Y4[1] = __ldg((const uint4*)&g_yf16[(size_t)s01 * 64 + yoff]);
        Y4[2] = __ldg((const uint4*)&g_yf16[(size_t)s10 * 64 + yoff]);
        Y4[3] = __ldg((const uint4*)&g_yf16[(size_t)s11 * 64 + yoff]);
        const int ct00 = t00, ct01 = t01, ct10 = t10, ct11 = t11;

        float acc[2][4][4];
#pragma unroll
        for (int i = 0; i < 2; ++i)
#pragma unroll
            for (int j = 0; j < 4; ++j)
#pragma unroll
                for (int q = 0; q < 4; ++q) acc[i][j][q] = 0.f;

        // ---------- GEMM1': tail[32,48] @ W1t ----------
#pragma unroll
        for (int ks = 0; ks < 3; ++ks) {
#pragma unroll
            for (int jj = 0; jj < 2; ++jj) {
                const uint32_t* b = &w1f[(ks * 2 + jj) * 4];
                mma_f16(acc[0][jj * 2],     &tailA[(0 * 3 + ks) * 4], b);
                mma_f16(acc[0][jj * 2 + 1], &tailA[(0 * 3 + ks) * 4], b + 2);
                mma_f16(acc[1][jj * 2],     &tailA[(1 * 3 + ks) * 4], b);
                mma_f16(acc[1][jj * 2 + 1], &tailA[(1 * 3 + ks) * 4], b + 2);
            }
        }

        // ---- prefetch next tile's tail frags + indices ----
        {
            const int nxt = tile + step;
            if (nxt < NT32) {
                const uint32_t* tf = g_tfrag + (size_t)nxt * 768 + lane;
#pragma unroll
                for (int p = 0; p < 24; ++p) tailN[p] = __ldg(&tf[p * 32]);
                const int nb = nxt * EK_M;
                s00 = __ldg(&ei[nb + crow]);
                s01 = __ldg(&ei[nb + crow + 8]);
                s10 = __ldg(&ei[nb + 16 + crow]);
                s11 = __ldg(&ei[nb + 24 + crow]);
                t00 = __ldg(&ei[NE + nb + crow]);
                t01 = __ldg(&ei[NE + nb + crow + 8]);
                t10 = __ldg(&ei[NE + nb + 16 + crow]);
                t11 = __ldg(&ei[NE + nb + 24 + crow]);
            }
        }

        // ---------- epilogue 1: relu(acc + Y + b1) -> H (f16) ----------
#pragma unroll
        for (int mf = 0; mf < 2; ++mf) {
            int r0 = mf * 16 + crow, r1 = r0 + 8;
#pragma unroll
            for (int j = 0; j < 4; ++j) {
                int n = nbase + j * 8 + ccol;
                uint32_t yu0 = ((const uint32_t*)&Y4[mf * 2 + 0])[j];
                uint32_t yu1 = ((const uint32_t*)&Y4[mf * 2 + 1])[j];
                __half2 y0 = *reinterpret_cast<__half2*>(&yu0);
                __half2 y1 = *reinterpret_cast<__half2*>(&yu1);
                float v0 = fmaxf(acc[mf][j][0] + __low2float(y0)  + b1s[n],     0.f);
                float v1 = fmaxf(acc[mf][j][1] + __high2float(y0) + b1s[n + 1], 0.f);
                float v2 = fmaxf(acc[mf][j][2] + __low2float(y1)  + b1s[n],     0.f);
                float v3 = fmaxf(acc[mf][j][3] + __high2float(y1) + b1s[n + 1], 0.f);
                *(__half2*)(smc + (hBase - smb) + 2 * (r0 * LDH + n)) = __floats2half2_rn(v0, v1);
                *(__half2*)(smc + (hBase - smb) + 2 * (r1 * LDH + n)) = __floats2half2_rn(v2, v3);
            }
        }
        GBAR(barId);

        // ---------- GEMM2: D2 = H(128) @ W2 ----------
#pragma unroll
        for (int i = 0; i < 2; ++i)
#pragma unroll
            for (int j = 0; j < 4; ++j)
#pragma unroll
                for (int q = 0; q < 4; ++q) acc[i][j][q] = 0.f;

#pragma unroll
        for (int ks = 0; ks < 8; ++ks) {
            const uint32_t kOff = (uint32_t)(ks * 16) * 2;
            uint32_t a0[4], a1[4];
            ldsm_x4(a0[0], a0[1], a0[2], a0[3], hBase + hRow0 + kOff);
            ldsm_x4(a1[0], a1[1], a1[2], a1[3], hBase + hRow1 + kOff);
#pragma unroll
            for (int jj = 0; jj < 2; ++jj) {
                const uint32_t nOff = (uint32_t)((nbase + jj * 16) * LDH) * 2;
                uint32_t b[4];
                ldsm_x4(b[0], b[1], b[2], b[3], smb + SM_W2 + b2LaneOff + nOff + kOff);
                mma_f16(acc[0][jj * 2],     a0, b);
                mma_f16(acc[0][jj * 2 + 1], a0, b + 2);
                mma_f16(acc[1][jj * 2],     a1, b);
                mma_f16(acc[1][jj * 2 + 1], a1, b + 2);
            }
        }

        // ---------- epilogue 2: pair-shuffled red.v4 scatter ----------
#pragma unroll
        for (int mf = 0; mf < 2; ++mf) {
            int tg0 = (mf == 0) ? ct00 : ct10;
            int tg1 = (mf == 0) ? ct01 : ct11;
            size_t ga0 = __cvta_generic_to_global(&g_agg[(size_t)tg0 * 128]);
            size_t ga1 = __cvta_generic_to_global(&g_agg[(size_t)tg1 * 128]);
#pragma unroll
            for (int j = 0; j < 4; ++j) {
                int n = nbase + j * 8 + ccol;
                float v0 = acc[mf][j][0] + b2s[n];
                float v1 = acc[mf][j][1] + b2s[n + 1];
                float v2 = acc[mf][j][2] + b2s[n];
                float v3 = acc[mf][j][3] + b2s[n + 1];
                // exchange with partner lane (lane^1): same target rows, cols +/-2
                float o0 = __shfl_xor_sync(0xffffffffu, v0, 1);
                float o1 = __shfl_xor_sync(0xffffffffu, v1, 1);
                float o2 = __shfl_xor_sync(0xffffffffu, v2, 1);
                float o3 = __shfl_xor_sync(0xffffffffu, v3, 1);
                if (evenLane) {
                    int nE = nbase + j * 8 + ccolE;
                    asm volatile("red.global.add.v4.f32 [%0], {%1,%2,%3,%4};"
                                 :: "l"(ga0 + (size_t)nE * 4),
                                    "f"(v0), "f"(v1), "f"(o0), "f"(o1) : "memory");
                    asm volatile("red.global.add.v4.f32 [%0], {%1,%2,%3,%4};"
                                 :: "l"(ga1 + (size_t)nE * 4),
                                    "f"(v2), "f"(v3), "f"(o2), "f"(o3) : "memory");
                }
            }
        }
        GBAR(barId);

#pragma unroll
        for (int i = 0; i < 24; ++i) tailA[i] = tailN[i];
    }
}

// ================= NODE KERNEL (R16 version, 2 CTAs/SM) =================
#define NLDB 136
#define NW0  0
#define NW1  34816
#define NVS  69632
#define NMS  87040
#define NODE_SMEM_BYTES 104448

__device__ __forceinline__ void hgemm1_128(uint32_t bBase, uint32_t aAddr,
                                           int nbase, float acc[8][4]) {
#pragma unroll
    for (int j = 0; j < 8; ++j)
#pragma unroll
        for (int q = 0; q < 4; ++q) acc[j][q] = 0.f;
#pragma unroll
    for (int ks = 0; ks < 8; ++ks) {
        const uint32_t kOff = (uint32_t)(ks * 16) * 2;
        uint32_t a[4];
        ldsm_x4(a[0], a[1], a[2], a[3], aAddr + kOff);
#pragma unroll
        for (int jj = 0; jj < 4; ++jj) {
            const uint32_t nOff = (uint32_t)((nbase + jj * 16) * NLDB) * 2;
            uint32_t b[4];
            ldsm_x4(b[0], b[1], b[2], b[3], bBase + nOff + kOff);
            mma_f16(acc[2 * jj],     a, b);
            mma_f16(acc[2 * jj + 1], a, b + 2);
        }
    }
}

__device__ __forceinline__ void node_stageW(char* smc, int slot, int mat, int tid) {
    const uint4* src = (const uint4*)(g_wf16 + mat * 8192);
    char* dst = smc + (slot ? NW1 : NW0);
    for (int idx = tid; idx < 128 * 16; idx += 256) {
        int n = idx >> 4, g = idx & 15;
        uint4 v = __ldg(&src[idx]);
        *(uint4*)(dst + n * (NLDB * 2) + g * 16) = v;
    }
}

__global__ __launch_bounds__(256, 2)
void node_kernel(const float* __restrict__ bih, const float* __restrict__ bhh,
                 const float* __restrict__ ob, float* __restrict__ out)
{
    extern __shared__ char smc[];
    const uint32_t smb = smem_u32(smc);
    const int tid = threadIdx.x, wid = tid >> 5, lane = tid & 31;
    const int m0 = (wid & 3) * 16, nbase = (wid >> 2) * 64;
    const int base = blockIdx.x * 64;
    const int crow = lane >> 2, ccol = (lane & 3) * 2;

    node_stageW(smc, 0, 0, tid);       // r -> slot0
    node_stageW(smc, 1, 2, tid);       // n -> slot1
    for (int idx = tid; idx < 64 * 64; idx += 256) {
        int m = idx >> 6, kp = idx & 63;
        int nd = base + m;
        float a0 = 0.f, a1 = 0.f;
        if (nd < NN) {
            float inv = 1.0f / fmaxf(g_cnt[nd], 1.0f);
            a0 = g_agg[(size_t)nd * 128 + 2 * kp] * inv;
            a1 = g_agg[(size_t)nd * 128 + 2 * kp + 1] * inv;
        }
        *(uint32_t*)(smc + NVS + 2 * (m * NLDB + 2 * kp)) = h2u(a0, a1);
    }
    __syncthreads();

    const uint32_t aRow = (uint32_t)((m0 + (lane & 15)) * NLDB + ((lane >> 4) << 3)) * 2;
    const uint32_t bRow = (uint32_t)((lane & 7) + ((lane >> 4) << 3));
    const uint32_t bLane = (uint32_t)(bRow * NLDB + (((lane >> 3) & 1) << 3)) * 2;

    float acc[8][4], rg[8][4], ng[8][4];

    hgemm1_128(smb + NW0 + bLane, smb + NVS + aRow, nbase, acc);
#pragma unroll
    for (int j = 0; j < 8; ++j) {
        int n = nbase + j * 8 + ccol;
        rg[j][0] = sigm(acc[j][0] + __ldg(&bih[n])     + __ldg(&bhh[n]));
        rg[j][1] = sigm(acc[j][1] + __ldg(&bih[n + 1]) + __ldg(&bhh[n + 1]));
        rg[j][2] = sigm(acc[j][2] + __ldg(&bih[n])     + __ldg(&bhh[n]));
        rg[j][3] = sigm(acc[j][3] + __ldg(&bih[n + 1]) + __ldg(&bhh[n + 1]));
    }

    hgemm1_128(smb + NW1 + bLane, smb + NVS + aRow, nbase, acc);
#pragma unroll
    for (int j = 0; j < 8; ++j) {
        int n = 256 + nbase + j * 8 + ccol;
        ng[j][0] = tanhf(acc[j][0] + __ldg(&bih[n])     + rg[j][0] * __ldg(&bhh[n]));
        ng[j][1] = tanhf(acc[j][1] + __ldg(&bih[n + 1]) + rg[j][1] * __ldg(&bhh[n + 1]));
        ng[j][2] = tanhf(acc[j][2] + __ldg(&bih[n])     + rg[j][2] * __ldg(&bhh[n]));
        ng[j][3] = tanhf(acc[j][3] + __ldg(&bih[n + 1]) + rg[j][3] * __ldg(&bhh[n + 1]));
    }
    __syncthreads();

    node_stageW(smc, 0, 1, tid);       // z -> slot0
    node_stageW(smc, 1, 3, tid);       // out -> slot1
    __syncthreads();

    hgemm1_128(smb + NW0 + bLane, smb + NVS + aRow, nbase, acc);
    {
        int r0 = m0 + crow, r1 = m0 + crow + 8;
#pragma unroll
        for (int j = 0; j < 8; ++j) {
            int nl = nbase + j * 8 + ccol;
            int n = 128 + nl;
            float z0 = sigm(acc[j][0] + __ldg(&bih[n])     + __ldg(&bhh[n]));
            float z1 = sigm(acc[j][1] + __ldg(&bih[n + 1]) + __ldg(&bhh[n + 1]));
            float z2 = sigm(acc[j][2] + __ldg(&bih[n])     + __ldg(&bhh[n]));
            float z3 = sigm(acc[j][3] + __ldg(&bih[n + 1]) + __ldg(&bhh[n + 1]));
            *(uint32_t*)(smc + NMS + 2 * (r0 * NLDB + nl)) =
                h2u((1.f - z0) * ng[j][0], (1.f - z1) * ng[j][1]);
            *(uint32_t*)(smc + NMS + 2 * (r1 * NLDB + nl)) =
                h2u((1.f - z2) * ng[j][2], (1.f - z3) * ng[j][3]);
        }
    }
    __syncthreads();

    hgemm1_128(smb + NW1 + bLane, smb + NMS + aRow, nbase, acc);
    {
        int r0 = m0 + crow, r1 = m0 + crow + 8;
        int nd0 = base + r0, nd1 = base + r1;
#pragma unroll
        for (int j = 0; j < 8; ++j) {
            int n = nbase + j * 8 + ccol;
            float o0 = __ldg(&ob[n]), o1 = __ldg(&ob[n + 1]);
            if (nd0 < NN)
                *(float2*)&out[(size_t)nd0 * 128 + n] = make_float2(acc[j][0] + o0, acc[j][1] + o1);
            if (nd1 < NN)
                *(float2*)&out[(size_t)nd1 * 128 + n] = make_float2(acc[j][2] + o0, acc[j][3] + o1);
        }
    }
}

// ================= launch =================
extern "C" void kernel_launch(void* const* d_in, const int* in_sizes, int n_in,
                              void* d_out, int out_size) {
    const float* x     = (const float*)d_in[0];
    const float* eattr = (const float*)d_in[1];
    const float* t     = (const float*)d_in[2];
    const float* tw    = (const float*)d_in[3];
    const float* tb    = (const float*)d_in[4];
    const float* w1    = (const float*)d_in[5];
    const float* b1    = (const float*)d_in[6];
    const float* w2    = (const float*)d_in[7];
    const float* b2    = (const float*)d_in[8];
    const float* wih   = (const float*)d_in[9];
    const float* bih   = (const float*)d_in[11];
    const float* bhh   = (const float*)d_in[12];
    const float* ow    = (const float*)d_in[13];
    const float* ob    = (const float*)d_in[14];
    const int*   ei    = (const int*)d_in[15];
    float* out = (float*)d_out;

    cudaFuncSetAttribute(edge_kernel, cudaFuncAttributeMaxDynamicSharedMemorySize, EDGE_SMEM_BYTES);
    cudaFuncSetAttribute(node_kernel, cudaFuncAttributeMaxDynamicSharedMemorySize, NODE_SMEM_BYTES);
    cudaFuncSetAttribute(prep_kernel, cudaFuncAttributeMaxDynamicSharedMemorySize, PREP_SMEM_BYTES);

    zero_kernel<<<256, 256>>>();
    prep_kernel<<<NPRE + NYB + NWB, 256, PREP_SMEM_BYTES>>>(eattr, t, tw, tb, ei, x, w1, wih, ow);
    edge_kernel<<<148, 384, EDGE_SMEM_BYTES>>>(w1, b1, w2, b2, ei);
    node_kernel<<<(NN + 63) / 64, 256, NODE_SMEM_BYTES>>>(bih, bhh, ob, out);
}